// round 1
// baseline (speedup 1.0000x reference)
#include <cuda_runtime.h>
#include <math.h>

#define TT    4096      // BATCH * SEQ tokens
#define HID   4096
#define NH    32
#define NKV   8
#define HD    128
#define QKVD  6144      // (32 + 16) * 128
#define SEQ   1024
#define NB    4

// Scratch (static device globals; no runtime allocation)
__device__ float g_qkv[(size_t)TT * QKVD];   // 96 MB
__device__ float g_attn[(size_t)TT * HID];   // 64 MB

// ---------------------------------------------------------------------------
// SGEMM (NT): C[M,N] = A[M,K] @ B[N,K]^T, all row-major, fp32.
// 128x128 block tile, BK=16, 256 threads, 8x8 per thread (split-4 columns).
// ---------------------------------------------------------------------------
template<int BM, int BN, int BK>
__global__ __launch_bounds__(256, 2) void sgemm_nt(const float* __restrict__ A,
                                                   const float* __restrict__ B,
                                                   float* __restrict__ C,
                                                   int M, int N, int K) {
    __shared__ float As[BK][BM];
    __shared__ float Bs[BK][BN];
    const int tid = threadIdx.x;
    const int tx = tid & 15;
    const int ty = tid >> 4;
    const int bm = blockIdx.y * BM;
    const int bn = blockIdx.x * BN;

    float acc[8][8];
#pragma unroll
    for (int i = 0; i < 8; i++)
#pragma unroll
        for (int j = 0; j < 8; j++) acc[i][j] = 0.f;

    for (int k0 = 0; k0 < K; k0 += BK) {
        // load A tile (BM x BK), store transposed into As[k][m]
#pragma unroll
        for (int it = 0; it < (BM * BK) / 1024; ++it) {
            int v = tid + it * 256;
            int row = v >> 2;        // BK/4 == 4 cols of float4
            int c4 = v & 3;
            float4 f = *reinterpret_cast<const float4*>(&A[(size_t)(bm + row) * K + k0 + c4 * 4]);
            As[c4 * 4 + 0][row] = f.x;
            As[c4 * 4 + 1][row] = f.y;
            As[c4 * 4 + 2][row] = f.z;
            As[c4 * 4 + 3][row] = f.w;
        }
#pragma unroll
        for (int it = 0; it < (BN * BK) / 1024; ++it) {
            int v = tid + it * 256;
            int row = v >> 2;
            int c4 = v & 3;
            float4 f = *reinterpret_cast<const float4*>(&B[(size_t)(bn + row) * K + k0 + c4 * 4]);
            Bs[c4 * 4 + 0][row] = f.x;
            Bs[c4 * 4 + 1][row] = f.y;
            Bs[c4 * 4 + 2][row] = f.z;
            Bs[c4 * 4 + 3][row] = f.w;
        }
        __syncthreads();
#pragma unroll
        for (int kk = 0; kk < BK; ++kk) {
            float a[8], b[8];
            *reinterpret_cast<float4*>(&a[0]) = *reinterpret_cast<const float4*>(&As[kk][ty * 4]);
            *reinterpret_cast<float4*>(&a[4]) = *reinterpret_cast<const float4*>(&As[kk][64 + ty * 4]);
            *reinterpret_cast<float4*>(&b[0]) = *reinterpret_cast<const float4*>(&Bs[kk][tx * 4]);
            *reinterpret_cast<float4*>(&b[4]) = *reinterpret_cast<const float4*>(&Bs[kk][64 + tx * 4]);
#pragma unroll
            for (int i = 0; i < 8; i++)
#pragma unroll
                for (int j = 0; j < 8; j++) acc[i][j] = fmaf(a[i], b[j], acc[i][j]);
        }
        __syncthreads();
    }

#pragma unroll
    for (int ih = 0; ih < 2; ih++)
#pragma unroll
        for (int i = 0; i < 4; i++) {
            int row = bm + ih * 64 + ty * 4 + i;
#pragma unroll
            for (int jh = 0; jh < 2; jh++) {
                float4 o = make_float4(acc[ih * 4 + i][jh * 4 + 0], acc[ih * 4 + i][jh * 4 + 1],
                                       acc[ih * 4 + i][jh * 4 + 2], acc[ih * 4 + i][jh * 4 + 3]);
                *reinterpret_cast<float4*>(&C[(size_t)row * N + bn + jh * 64 + tx * 4]) = o;
            }
        }
}

// ---------------------------------------------------------------------------
// RoPE (rotate-half) applied in place to the Q and K parts of qkv.
// Q heads 0..31 and K heads 32..39 are contiguous: offset h*HD works for h<40.
// ---------------------------------------------------------------------------
__global__ void rope_kernel(float* __restrict__ qkv) {
    const int HALF = HD / 2;
    int idx = blockIdx.x * blockDim.x + threadIdx.x;
    int total = TT * (NH + NKV) * HALF;
    if (idx >= total) return;
    int i = idx % HALF;
    int r = idx / HALF;
    int h = r % (NH + NKV);
    int t = r / (NH + NKV);
    int pos = t & (SEQ - 1);

    float e = (float)(2 * i) * (1.0f / (float)HD);
    float invf = 1.0f / powf(10000.0f, e);
    float ang = (float)pos * invf;
    float s, c;
    sincosf(ang, &s, &c);

    float* base = qkv + (size_t)t * QKVD + h * HD + i;
    float x1 = base[0];
    float x2 = base[HALF];
    base[0]    = x1 * c - x2 * s;
    base[HALF] = x2 * c + x1 * s;
}

// ---------------------------------------------------------------------------
// Causal GQA flash attention, fp32.
// Grid: (S/64, NH, NB). 256 threads. 64 q-rows x full D=128 per block.
// Smem (dynamic): Qs[64][132], Kt[128][64] (transposed), Vs[64][128], Ps[64][64]
// ---------------------------------------------------------------------------
#define QS_STRIDE 132
#define ATTN_SMEM_FLOATS (64 * QS_STRIDE + 128 * 64 + 64 * 128 + 64 * 64)

__global__ __launch_bounds__(256) void attn_kernel(const float* __restrict__ qkv,
                                                   float* __restrict__ out) {
    extern __shared__ float smem[];
    float* Qs = smem;                       // [64][132]
    float* Kt = Qs + 64 * QS_STRIDE;        // [128][64]
    float* Vs = Kt + 128 * 64;              // [64][128]
    float* Ps = Vs + 64 * 128;              // [64][64]

    const int qtile = gridDim.x - 1 - blockIdx.x;   // heavy tiles first
    const int h = blockIdx.y;
    const int b = blockIdx.z;
    const int kvh = h >> 2;                 // groups = 4
    const int tid = threadIdx.x;
    const int tx = tid & 15;
    const int ty = tid >> 4;

    // load Q tile (64 x 128)
    for (int v = tid; v < 64 * 32; v += 256) {
        int r = v >> 5;
        int c4 = v & 31;
        int t = b * SEQ + qtile * 64 + r;
        float4 f = *reinterpret_cast<const float4*>(&qkv[(size_t)t * QKVD + h * HD + c4 * 4]);
        *reinterpret_cast<float4*>(&Qs[r * QS_STRIDE + c4 * 4]) = f;
    }

    float m_i[4], l_i[4], acc[4][8];
#pragma unroll
    for (int i = 0; i < 4; i++) {
        m_i[i] = -1e30f;
        l_i[i] = 0.f;
#pragma unroll
        for (int j = 0; j < 8; j++) acc[i][j] = 0.f;
    }
    const float scale = 0.0883883476483184f;   // 128^-0.5

    for (int kt = 0; kt <= qtile; ++kt) {
        __syncthreads();   // prev PV done (and Q loaded on first iter)
        // load K tile transposed and V tile
        for (int v = tid; v < 64 * 32; v += 256) {
            int r = v >> 5;
            int c4 = v & 31;
            int t = b * SEQ + kt * 64 + r;
            const float* kp = &qkv[(size_t)t * QKVD + HID + kvh * HD + c4 * 4];
            float4 kf = *reinterpret_cast<const float4*>(kp);
            Kt[(c4 * 4 + 0) * 64 + r] = kf.x;
            Kt[(c4 * 4 + 1) * 64 + r] = kf.y;
            Kt[(c4 * 4 + 2) * 64 + r] = kf.z;
            Kt[(c4 * 4 + 3) * 64 + r] = kf.w;
            const float* vp = &qkv[(size_t)t * QKVD + HID + NKV * HD + kvh * HD + c4 * 4];
            *reinterpret_cast<float4*>(&Vs[r * 128 + c4 * 4]) = *reinterpret_cast<const float4*>(vp);
        }
        __syncthreads();

        // scores: S[ty*4+i][tx*4+j] = Q row . K row
        float sc[4][4];
#pragma unroll
        for (int i = 0; i < 4; i++)
#pragma unroll
            for (int j = 0; j < 4; j++) sc[i][j] = 0.f;

#pragma unroll 4
        for (int kk = 0; kk < HD; kk += 4) {
            float qv[4][4], kv[4][4];
#pragma unroll
            for (int i = 0; i < 4; i++)
                *reinterpret_cast<float4*>(qv[i]) =
                    *reinterpret_cast<const float4*>(&Qs[(ty * 4 + i) * QS_STRIDE + kk]);
#pragma unroll
            for (int u = 0; u < 4; u++)
                *reinterpret_cast<float4*>(kv[u]) =
                    *reinterpret_cast<const float4*>(&Kt[(kk + u) * 64 + tx * 4]);
#pragma unroll
            for (int i = 0; i < 4; i++)
#pragma unroll
                for (int u = 0; u < 4; u++)
#pragma unroll
                    for (int j = 0; j < 4; j++)
                        sc[i][j] = fmaf(qv[i][u], kv[u][j], sc[i][j]);
        }

#pragma unroll
        for (int i = 0; i < 4; i++)
#pragma unroll
            for (int j = 0; j < 4; j++) sc[i][j] *= scale;

        if (kt == qtile) {   // causal mask on diagonal tile
#pragma unroll
            for (int i = 0; i < 4; i++)
#pragma unroll
                for (int j = 0; j < 4; j++)
                    if (tx * 4 + j > ty * 4 + i) sc[i][j] = -1e30f;
        }

        // online softmax (rows spread across the 16 tx lanes of each half-warp)
#pragma unroll
        for (int i = 0; i < 4; i++) {
            float mx = fmaxf(fmaxf(sc[i][0], sc[i][1]), fmaxf(sc[i][2], sc[i][3]));
#pragma unroll
            for (int o = 8; o >= 1; o >>= 1)
                mx = fmaxf(mx, __shfl_xor_sync(0xffffffffu, mx, o));
            float m_new = fmaxf(m_i[i], mx);
            float p0 = __expf(sc[i][0] - m_new);
            float p1 = __expf(sc[i][1] - m_new);
            float p2 = __expf(sc[i][2] - m_new);
            float p3 = __expf(sc[i][3] - m_new);
            float rs = (p0 + p1) + (p2 + p3);
#pragma unroll
            for (int o = 8; o >= 1; o >>= 1)
                rs += __shfl_xor_sync(0xffffffffu, rs, o);
            float alpha = __expf(m_i[i] - m_new);
            l_i[i] = l_i[i] * alpha + rs;
            m_i[i] = m_new;
#pragma unroll
            for (int j = 0; j < 8; j++) acc[i][j] *= alpha;
            *reinterpret_cast<float4*>(&Ps[(ty * 4 + i) * 64 + tx * 4]) =
                make_float4(p0, p1, p2, p3);
        }
        __syncthreads();

        // PV: acc[i][0..3] += P @ V cols [tx*4..], acc[i][4..7] += cols [64+tx*4..]
#pragma unroll 4
        for (int kk = 0; kk < 64; kk += 4) {
            float pv[4][4], vv[4][8];
#pragma unroll
            for (int i = 0; i < 4; i++)
                *reinterpret_cast<float4*>(pv[i]) =
                    *reinterpret_cast<const float4*>(&Ps[(ty * 4 + i) * 64 + kk]);
#pragma unroll
            for (int u = 0; u < 4; u++) {
                *reinterpret_cast<float4*>(&vv[u][0]) =
                    *reinterpret_cast<const float4*>(&Vs[(kk + u) * 128 + tx * 4]);
                *reinterpret_cast<float4*>(&vv[u][4]) =
                    *reinterpret_cast<const float4*>(&Vs[(kk + u) * 128 + 64 + tx * 4]);
            }
#pragma unroll
            for (int i = 0; i < 4; i++)
#pragma unroll
                for (int u = 0; u < 4; u++)
#pragma unroll
                    for (int j = 0; j < 8; j++)
                        acc[i][j] = fmaf(pv[i][u], vv[u][j], acc[i][j]);
        }
    }

    // epilogue: normalize and write to g_attn [T, H*D]
#pragma unroll
    for (int i = 0; i < 4; i++) {
        float inv = 1.0f / l_i[i];
        int t = b * SEQ + qtile * 64 + ty * 4 + i;
        float* op = &out[(size_t)t * HID + h * HD];
        *reinterpret_cast<float4*>(&op[tx * 4]) =
            make_float4(acc[i][0] * inv, acc[i][1] * inv, acc[i][2] * inv, acc[i][3] * inv);
        *reinterpret_cast<float4*>(&op[64 + tx * 4]) =
            make_float4(acc[i][4] * inv, acc[i][5] * inv, acc[i][6] * inv, acc[i][7] * inv);
    }
}

// ---------------------------------------------------------------------------
extern "C" void kernel_launch(void* const* d_in, const int* in_sizes, int n_in,
                              void* d_out, int out_size) {
    const float* hs    = (const float*)d_in[0];   // [4096, 4096]
    const float* w_qkv = (const float*)d_in[1];   // [6144, 4096]
    const float* w_o   = (const float*)d_in[2];   // [4096, 4096]
    float* out = (float*)d_out;                   // [4096, 4096]

    float* qkv = nullptr;
    float* attn = nullptr;
    cudaGetSymbolAddress((void**)&qkv, g_qkv);
    cudaGetSymbolAddress((void**)&attn, g_attn);

    // 1) QKV projection: [4096, 6144]
    {
        dim3 grid(QKVD / 128, TT / 128);
        sgemm_nt<128, 128, 16><<<grid, 256>>>(hs, w_qkv, qkv, TT, QKVD, HID);
    }

    // 2) RoPE on q and k (in place)
    {
        int total = TT * (NH + NKV) * (HD / 2);
        rope_kernel<<<(total + 255) / 256, 256>>>(qkv);
    }

    // 3) Causal GQA attention -> g_attn [T, H*D]
    {
        static const int smem_bytes = ATTN_SMEM_FLOATS * (int)sizeof(float);
        cudaFuncSetAttribute(attn_kernel, cudaFuncAttributeMaxDynamicSharedMemorySize, smem_bytes);
        dim3 grid(SEQ / 64, NH, NB);
        attn_kernel<<<grid, 256, smem_bytes>>>(qkv, attn);
    }

    // 4) Output projection: out = attn @ w_o^T
    {
        dim3 grid(HID / 128, TT / 128);
        sgemm_nt<128, 128, 16><<<grid, 256>>>(attn, w_o, out, TT, HID, HID);
    }
}

// round 4
// speedup vs baseline: 2.1167x; 2.1167x over previous
#include <cuda_runtime.h>
#include <cuda_bf16.h>
#include <math.h>
#include <stdint.h>

#define TT    4096      // BATCH * SEQ tokens
#define HID   4096
#define NH    32
#define NKV   8
#define HD    128
#define QKVD  6144      // (32 + 16) * 128
#define SEQ   1024
#define NB    4

// Scratch (static device globals; no runtime allocation)
__device__ float g_qkv[(size_t)TT * QKVD];   // 96 MB
__device__ float g_attn[(size_t)TT * HID];   // 64 MB

// ===========================================================================
// mma.sync helpers (sm_80+ ISA, compiles at compute_103)
// ===========================================================================
__device__ __forceinline__ uint32_t smem_u32(const void* p) {
    uint32_t a;
    asm("{ .reg .u64 t; cvta.to.shared.u64 t, %1; cvt.u32.u64 %0, t; }"
        : "=r"(a) : "l"(p));
    return a;
}

__device__ __forceinline__ void ldsm_x4(uint32_t* r, uint32_t addr) {
    asm volatile("ldmatrix.sync.aligned.m8n8.x4.shared.b16 {%0,%1,%2,%3}, [%4];"
                 : "=r"(r[0]), "=r"(r[1]), "=r"(r[2]), "=r"(r[3]) : "r"(addr));
}

__device__ __forceinline__ void mma_bf16(float* c, const uint32_t* a,
                                         uint32_t b0, uint32_t b1) {
    asm volatile(
        "mma.sync.aligned.m16n8k16.row.col.f32.bf16.bf16.f32 "
        "{%0,%1,%2,%3}, {%4,%5,%6,%7}, {%8,%9}, {%0,%1,%2,%3};"
        : "+f"(c[0]), "+f"(c[1]), "+f"(c[2]), "+f"(c[3])
        : "r"(a[0]), "r"(a[1]), "r"(a[2]), "r"(a[3]), "r"(b0), "r"(b1));
}

// split 4 fp32 -> packed hi bf16x2 pair + lo bf16x2 pair
__device__ __forceinline__ void split4(float4 f, uint32_t* hi, uint32_t* lo) {
    uint32_t x0 = __float_as_uint(f.x), x1 = __float_as_uint(f.y);
    uint32_t x2 = __float_as_uint(f.z), x3 = __float_as_uint(f.w);
    hi[0] = __byte_perm(x0, x1, 0x7632);   // [bf16(f.x), bf16(f.y)] truncated
    hi[1] = __byte_perm(x2, x3, 0x7632);
    float l0 = f.x - __uint_as_float(x0 & 0xFFFF0000u);
    float l1 = f.y - __uint_as_float(x1 & 0xFFFF0000u);
    float l2 = f.z - __uint_as_float(x2 & 0xFFFF0000u);
    float l3 = f.w - __uint_as_float(x3 & 0xFFFF0000u);
    __nv_bfloat162 b0 = __floats2bfloat162_rn(l0, l1);
    __nv_bfloat162 b1 = __floats2bfloat162_rn(l2, l3);
    lo[0] = *reinterpret_cast<uint32_t*>(&b0);
    lo[1] = *reinterpret_cast<uint32_t*>(&b1);
}

// ===========================================================================
// bf16x3 split GEMM (NT): C[M,N] = A[M,K] @ B[N,K]^T, fp32 in/out.
// C = Ahi*Bhi + Ahi*Blo + Alo*Bhi via mma.sync bf16, fp32 accum in registers.
// CTA tile 128x128, BK=32, 256 threads (8 warps, 4Mx2N), warp tile 32x64.
// Smem: Ahi/Alo/Bhi/Blo each [128][40] bf16 (pad 40 -> conflict-free ldmatrix)
// ===========================================================================
#define GBM 128
#define GBN 128
#define GKB 32
#define GSTRIDE 40
#define TILE_ELE (128 * GSTRIDE)
#define GEMM_SMEM (4 * TILE_ELE * 2)

__global__ __launch_bounds__(256) void gemm_bf16x3(const float* __restrict__ A,
                                                   const float* __restrict__ B,
                                                   float* __restrict__ C,
                                                   int M, int N, int K) {
    extern __shared__ __nv_bfloat16 sm[];
    __nv_bfloat16* sAhi = sm;
    __nv_bfloat16* sAlo = sm + TILE_ELE;
    __nv_bfloat16* sBhi = sm + 2 * TILE_ELE;
    __nv_bfloat16* sBlo = sm + 3 * TILE_ELE;

    const int tid = threadIdx.x;
    const int wid = tid >> 5;
    const int lane = tid & 31;
    const int wm = wid & 3;          // 0..3  -> m offset 32*wm
    const int wn = wid >> 2;         // 0..1  -> n offset 64*wn
    const int bm = blockIdx.y * GBM;
    const int bn = blockIdx.x * GBN;

    // gmem load indexing: 1024 float4 per (128x32) tile, 4 per thread
    const int lrow = tid >> 3;         // 0..31 base row (step 32)
    const int lc4 = tid & 7;           // float4 column 0..7

    float acc[2][8][4];
#pragma unroll
    for (int i = 0; i < 2; i++)
#pragma unroll
        for (int j = 0; j < 8; j++)
#pragma unroll
            for (int q = 0; q < 4; q++) acc[i][j][q] = 0.f;

    // smem addresses for ldmatrix (byte offsets, computed once)
    const uint32_t sb = smem_u32(sm);
    const uint32_t aRow = wm * 32 + (lane & 15);
    const uint32_t aCol = (lane >> 4) * 8;
    const uint32_t aOffB = (aRow * GSTRIDE + aCol) * 2;
    const uint32_t addrAhi = sb + aOffB;
    const uint32_t addrAlo = sb + TILE_ELE * 2 + aOffB;
    const uint32_t bRow = wn * 64 + (lane & 7) + ((lane >> 4) & 1) * 8;
    const uint32_t bCol = ((lane >> 3) & 1) * 8;
    const uint32_t bOffB = (bRow * GSTRIDE + bCol) * 2;
    const uint32_t addrBhi = sb + 2 * TILE_ELE * 2 + bOffB;
    const uint32_t addrBlo = sb + 3 * TILE_ELE * 2 + bOffB;

    const int NC = K / GKB;
    float4 pfA[4], pfB[4];

    // prefetch chunk 0
#pragma unroll
    for (int u = 0; u < 4; ++u) {
        int row = lrow + u * 32;
        pfA[u] = *reinterpret_cast<const float4*>(&A[(size_t)(bm + row) * K + lc4 * 4]);
        pfB[u] = *reinterpret_cast<const float4*>(&B[(size_t)(bn + row) * K + lc4 * 4]);
    }

    for (int kc = 0; kc < NC; ++kc) {
        // convert + store prefetched chunk to smem
#pragma unroll
        for (int u = 0; u < 4; ++u) {
            int row = lrow + u * 32;
            uint32_t hi[2], lo[2];
            uint32_t off = row * GSTRIDE + lc4 * 4;
            split4(pfA[u], hi, lo);
            *reinterpret_cast<uint2*>(&sAhi[off]) = make_uint2(hi[0], hi[1]);
            *reinterpret_cast<uint2*>(&sAlo[off]) = make_uint2(lo[0], lo[1]);
            split4(pfB[u], hi, lo);
            *reinterpret_cast<uint2*>(&sBhi[off]) = make_uint2(hi[0], hi[1]);
            *reinterpret_cast<uint2*>(&sBlo[off]) = make_uint2(lo[0], lo[1]);
        }
        __syncthreads();

        // prefetch next chunk (loads fly during the mma loop)
        if (kc + 1 < NC) {
            const int k0 = (kc + 1) * GKB;
#pragma unroll
            for (int u = 0; u < 4; ++u) {
                int row = lrow + u * 32;
                pfA[u] = *reinterpret_cast<const float4*>(&A[(size_t)(bm + row) * K + k0 + lc4 * 4]);
                pfB[u] = *reinterpret_cast<const float4*>(&B[(size_t)(bn + row) * K + k0 + lc4 * 4]);
            }
        }

        // MMA over the two k16 steps of this chunk
#pragma unroll
        for (int ks = 0; ks < 2; ++ks) {
            const uint32_t ko = ks * 32;   // 16 bf16 = 32 bytes
            uint32_t ah[2][4], al[2][4];
#pragma unroll
            for (int mt = 0; mt < 2; ++mt) {
                ldsm_x4(ah[mt], addrAhi + mt * (16 * GSTRIDE * 2) + ko);
                ldsm_x4(al[mt], addrAlo + mt * (16 * GSTRIDE * 2) + ko);
            }
            uint32_t bh[4][4], bl[4][4];
#pragma unroll
            for (int p = 0; p < 4; ++p) {
                ldsm_x4(bh[p], addrBhi + p * (16 * GSTRIDE * 2) + ko);
                ldsm_x4(bl[p], addrBlo + p * (16 * GSTRIDE * 2) + ko);
            }
#pragma unroll
            for (int mt = 0; mt < 2; ++mt)
#pragma unroll
                for (int nt = 0; nt < 8; ++nt) {
                    uint32_t h0 = bh[nt >> 1][(nt & 1) * 2];
                    uint32_t h1 = bh[nt >> 1][(nt & 1) * 2 + 1];
                    uint32_t l0 = bl[nt >> 1][(nt & 1) * 2];
                    uint32_t l1 = bl[nt >> 1][(nt & 1) * 2 + 1];
                    mma_bf16(acc[mt][nt], ah[mt], h0, h1);
                    mma_bf16(acc[mt][nt], ah[mt], l0, l1);
                    mma_bf16(acc[mt][nt], al[mt], h0, h1);
                }
        }
        __syncthreads();
    }

    // epilogue: c fragment -> C.  thread holds rows g, g+8; cols 2 consecutive
    const int g = lane >> 2;
    const int cc = (lane & 3) * 2;
#pragma unroll
    for (int mt = 0; mt < 2; ++mt) {
        int row0 = bm + wm * 32 + mt * 16 + g;
#pragma unroll
        for (int nt = 0; nt < 8; ++nt) {
            int col = bn + wn * 64 + nt * 8 + cc;
            *reinterpret_cast<float2*>(&C[(size_t)row0 * N + col]) =
                make_float2(acc[mt][nt][0], acc[mt][nt][1]);
            *reinterpret_cast<float2*>(&C[(size_t)(row0 + 8) * N + col]) =
                make_float2(acc[mt][nt][2], acc[mt][nt][3]);
        }
    }
}

// ---------------------------------------------------------------------------
// RoPE (rotate-half) applied in place to the Q and K parts of qkv.
// ---------------------------------------------------------------------------
__global__ void rope_kernel(float* __restrict__ qkv) {
    const int HALF = HD / 2;
    int idx = blockIdx.x * blockDim.x + threadIdx.x;
    int total = TT * (NH + NKV) * HALF;
    if (idx >= total) return;
    int i = idx % HALF;
    int r = idx / HALF;
    int h = r % (NH + NKV);
    int t = r / (NH + NKV);
    int pos = t & (SEQ - 1);

    float e = (float)(2 * i) * (1.0f / (float)HD);
    float invf = 1.0f / powf(10000.0f, e);
    float ang = (float)pos * invf;
    float s, c;
    sincosf(ang, &s, &c);

    float* base = qkv + (size_t)t * QKVD + h * HD + i;
    float x1 = base[0];
    float x2 = base[HALF];
    base[0]    = x1 * c - x2 * s;
    base[HALF] = x2 * c + x1 * s;
}

// ---------------------------------------------------------------------------
// Causal GQA flash attention, fp32.
// Grid: (S/64, NH, NB). 256 threads. 64 q-rows x full D=128 per block.
// ---------------------------------------------------------------------------
#define QS_STRIDE 132
#define ATTN_SMEM_FLOATS (64 * QS_STRIDE + 128 * 64 + 64 * 128 + 64 * 64)

__global__ __launch_bounds__(256) void attn_kernel(const float* __restrict__ qkv,
                                                   float* __restrict__ out) {
    extern __shared__ float smemf[];
    float* Qs = smemf;                      // [64][132]
    float* Kt = Qs + 64 * QS_STRIDE;        // [128][64]
    float* Vs = Kt + 128 * 64;              // [64][128]
    float* Ps = Vs + 64 * 128;              // [64][64]

    const int qtile = gridDim.x - 1 - blockIdx.x;   // heavy tiles first
    const int h = blockIdx.y;
    const int b = blockIdx.z;
    const int kvh = h >> 2;                 // groups = 4
    const int tid = threadIdx.x;
    const int tx = tid & 15;
    const int ty = tid >> 4;

    for (int v = tid; v < 64 * 32; v += 256) {
        int r = v >> 5;
        int c4 = v & 31;
        int t = b * SEQ + qtile * 64 + r;
        float4 f = *reinterpret_cast<const float4*>(&qkv[(size_t)t * QKVD + h * HD + c4 * 4]);
        *reinterpret_cast<float4*>(&Qs[r * QS_STRIDE + c4 * 4]) = f;
    }

    float m_i[4], l_i[4], acc[4][8];
#pragma unroll
    for (int i = 0; i < 4; i++) {
        m_i[i] = -1e30f;
        l_i[i] = 0.f;
#pragma unroll
        for (int j = 0; j < 8; j++) acc[i][j] = 0.f;
    }
    const float scale = 0.0883883476483184f;   // 128^-0.5

    for (int kt = 0; kt <= qtile; ++kt) {
        __syncthreads();
        for (int v = tid; v < 64 * 32; v += 256) {
            int r = v >> 5;
            int c4 = v & 31;
            int t = b * SEQ + kt * 64 + r;
            const float* kp = &qkv[(size_t)t * QKVD + HID + kvh * HD + c4 * 4];
            float4 kf = *reinterpret_cast<const float4*>(kp);
            Kt[(c4 * 4 + 0) * 64 + r] = kf.x;
            Kt[(c4 * 4 + 1) * 64 + r] = kf.y;
            Kt[(c4 * 4 + 2) * 64 + r] = kf.z;
            Kt[(c4 * 4 + 3) * 64 + r] = kf.w;
            const float* vp = &qkv[(size_t)t * QKVD + HID + NKV * HD + kvh * HD + c4 * 4];
            *reinterpret_cast<float4*>(&Vs[r * 128 + c4 * 4]) = *reinterpret_cast<const float4*>(vp);
        }
        __syncthreads();

        float sc[4][4];
#pragma unroll
        for (int i = 0; i < 4; i++)
#pragma unroll
            for (int j = 0; j < 4; j++) sc[i][j] = 0.f;

#pragma unroll 4
        for (int kk = 0; kk < HD; kk += 4) {
            float qv[4][4], kv[4][4];
#pragma unroll
            for (int i = 0; i < 4; i++)
                *reinterpret_cast<float4*>(qv[i]) =
                    *reinterpret_cast<const float4*>(&Qs[(ty * 4 + i) * QS_STRIDE + kk]);
#pragma unroll
            for (int u = 0; u < 4; u++)
                *reinterpret_cast<float4*>(kv[u]) =
                    *reinterpret_cast<const float4*>(&Kt[(kk + u) * 64 + tx * 4]);
#pragma unroll
            for (int i = 0; i < 4; i++)
#pragma unroll
                for (int u = 0; u < 4; u++)
#pragma unroll
                    for (int j = 0; j < 4; j++)
                        sc[i][j] = fmaf(qv[i][u], kv[u][j], sc[i][j]);
        }

#pragma unroll
        for (int i = 0; i < 4; i++)
#pragma unroll
            for (int j = 0; j < 4; j++) sc[i][j] *= scale;

        if (kt == qtile) {
#pragma unroll
            for (int i = 0; i < 4; i++)
#pragma unroll
                for (int j = 0; j < 4; j++)
                    if (tx * 4 + j > ty * 4 + i) sc[i][j] = -1e30f;
        }

#pragma unroll
        for (int i = 0; i < 4; i++) {
            float mx = fmaxf(fmaxf(sc[i][0], sc[i][1]), fmaxf(sc[i][2], sc[i][3]));
#pragma unroll
            for (int o = 8; o >= 1; o >>= 1)
                mx = fmaxf(mx, __shfl_xor_sync(0xffffffffu, mx, o));
            float m_new = fmaxf(m_i[i], mx);
            float p0 = __expf(sc[i][0] - m_new);
            float p1 = __expf(sc[i][1] - m_new);
            float p2 = __expf(sc[i][2] - m_new);
            float p3 = __expf(sc[i][3] - m_new);
            float rs = (p0 + p1) + (p2 + p3);
#pragma unroll
            for (int o = 8; o >= 1; o >>= 1)
                rs += __shfl_xor_sync(0xffffffffu, rs, o);
            float alpha = __expf(m_i[i] - m_new);
            l_i[i] = l_i[i] * alpha + rs;
            m_i[i] = m_new;
#pragma unroll
            for (int j = 0; j < 8; j++) acc[i][j] *= alpha;
            *reinterpret_cast<float4*>(&Ps[(ty * 4 + i) * 64 + tx * 4]) =
                make_float4(p0, p1, p2, p3);
        }
        __syncthreads();

#pragma unroll 4
        for (int kk = 0; kk < 64; kk += 4) {
            float pv[4][4], vv[4][8];
#pragma unroll
            for (int i = 0; i < 4; i++)
                *reinterpret_cast<float4*>(pv[i]) =
                    *reinterpret_cast<const float4*>(&Ps[(ty * 4 + i) * 64 + kk]);
#pragma unroll
            for (int u = 0; u < 4; u++) {
                *reinterpret_cast<float4*>(&vv[u][0]) =
                    *reinterpret_cast<const float4*>(&Vs[(kk + u) * 128 + tx * 4]);
                *reinterpret_cast<float4*>(&vv[u][4]) =
                    *reinterpret_cast<const float4*>(&Vs[(kk + u) * 128 + 64 + tx * 4]);
            }
#pragma unroll
            for (int i = 0; i < 4; i++)
#pragma unroll
                for (int u = 0; u < 4; u++)
#pragma unroll
                    for (int j = 0; j < 8; j++)
                        acc[i][j] = fmaf(pv[i][u], vv[u][j], acc[i][j]);
        }
    }

#pragma unroll
    for (int i = 0; i < 4; i++) {
        float inv = 1.0f / l_i[i];
        int t = b * SEQ + qtile * 64 + ty * 4 + i;
        float* op = &out[(size_t)t * HID + h * HD];
        *reinterpret_cast<float4*>(&op[tx * 4]) =
            make_float4(acc[i][0] * inv, acc[i][1] * inv, acc[i][2] * inv, acc[i][3] * inv);
        *reinterpret_cast<float4*>(&op[64 + tx * 4]) =
            make_float4(acc[i][4] * inv, acc[i][5] * inv, acc[i][6] * inv, acc[i][7] * inv);
    }
}

// ---------------------------------------------------------------------------
extern "C" void kernel_launch(void* const* d_in, const int* in_sizes, int n_in,
                              void* d_out, int out_size) {
    const float* hs    = (const float*)d_in[0];   // [4096, 4096]
    const float* w_qkv = (const float*)d_in[1];   // [6144, 4096]
    const float* w_o   = (const float*)d_in[2];   // [4096, 4096]
    float* out = (float*)d_out;                   // [4096, 4096]

    float* qkv = nullptr;
    float* attn = nullptr;
    cudaGetSymbolAddress((void**)&qkv, g_qkv);
    cudaGetSymbolAddress((void**)&attn, g_attn);

    cudaFuncSetAttribute(gemm_bf16x3, cudaFuncAttributeMaxDynamicSharedMemorySize, GEMM_SMEM);

    // 1) QKV projection: [4096, 6144] = hs @ w_qkv^T (tensor cores, bf16x3)
    {
        dim3 grid(QKVD / GBN, TT / GBM);
        gemm_bf16x3<<<grid, 256, GEMM_SMEM>>>(hs, w_qkv, qkv, TT, QKVD, HID);
    }

    // 2) RoPE on q and k (in place)
    {
        int total = TT * (NH + NKV) * (HD / 2);
        rope_kernel<<<(total + 255) / 256, 256>>>(qkv);
    }

    // 3) Causal GQA attention -> g_attn [T, H*D]
    {
        static const int smem_bytes = ATTN_SMEM_FLOATS * (int)sizeof(float);
        cudaFuncSetAttribute(attn_kernel, cudaFuncAttributeMaxDynamicSharedMemorySize, smem_bytes);
        dim3 grid(SEQ / 64, NH, NB);
        attn_kernel<<<grid, 256, smem_bytes>>>(qkv, attn);
    }

    // 4) Output projection: out = attn @ w_o^T (tensor cores, bf16x3)
    {
        dim3 grid(HID / GBN, TT / GBM);
        gemm_bf16x3<<<grid, 256, GEMM_SMEM>>>(attn, w_o, out, TT, HID, HID);
    }
}

// round 5
// speedup vs baseline: 2.8118x; 1.3284x over previous
#include <cuda_runtime.h>
#include <cuda_bf16.h>
#include <math.h>
#include <stdint.h>

#define TT    4096      // BATCH * SEQ tokens
#define HID   4096
#define NH    32
#define NKV   8
#define HD    128
#define QKVD  6144      // (32 + 16) * 128
#define SEQ   1024
#define NB    4

// Scratch (static device globals; no runtime allocation)
__device__ float g_qkv[(size_t)TT * QKVD];   // 96 MB
__device__ float g_attn[(size_t)TT * HID];   // 64 MB
// split bf16 buffers (head-major)
__device__ __nv_bfloat16 g_qhi[(size_t)NB * NH * SEQ * HD];
__device__ __nv_bfloat16 g_qlo[(size_t)NB * NH * SEQ * HD];
__device__ __nv_bfloat16 g_khi[(size_t)NB * NKV * SEQ * HD];
__device__ __nv_bfloat16 g_klo[(size_t)NB * NKV * SEQ * HD];
__device__ __nv_bfloat16 g_vhi[(size_t)NB * NKV * SEQ * HD];
__device__ __nv_bfloat16 g_vlo[(size_t)NB * NKV * SEQ * HD];

// ===========================================================================
// helpers
// ===========================================================================
__device__ __forceinline__ uint32_t smem_u32(const void* p) {
    uint32_t a;
    asm("{ .reg .u64 t; cvta.to.shared.u64 t, %1; cvt.u32.u64 %0, t; }"
        : "=r"(a) : "l"(p));
    return a;
}
__device__ __forceinline__ void ldsm_x4(uint32_t* r, uint32_t addr) {
    asm volatile("ldmatrix.sync.aligned.m8n8.x4.shared.b16 {%0,%1,%2,%3}, [%4];"
                 : "=r"(r[0]), "=r"(r[1]), "=r"(r[2]), "=r"(r[3]) : "r"(addr));
}
__device__ __forceinline__ void ldsm_x4_t(uint32_t* r, uint32_t addr) {
    asm volatile("ldmatrix.sync.aligned.m8n8.x4.trans.shared.b16 {%0,%1,%2,%3}, [%4];"
                 : "=r"(r[0]), "=r"(r[1]), "=r"(r[2]), "=r"(r[3]) : "r"(addr));
}
__device__ __forceinline__ void mma_bf16(float* c, const uint32_t* a,
                                         uint32_t b0, uint32_t b1) {
    asm volatile(
        "mma.sync.aligned.m16n8k16.row.col.f32.bf16.bf16.f32 "
        "{%0,%1,%2,%3}, {%4,%5,%6,%7}, {%8,%9}, {%0,%1,%2,%3};"
        : "+f"(c[0]), "+f"(c[1]), "+f"(c[2]), "+f"(c[3])
        : "r"(a[0]), "r"(a[1]), "r"(a[2]), "r"(a[3]), "r"(b0), "r"(b1));
}
__device__ __forceinline__ void cp16(uint32_t dst, const void* src) {
    asm volatile("cp.async.cg.shared.global [%0], [%1], 16;" :: "r"(dst), "l"(src));
}
#define CP_COMMIT() asm volatile("cp.async.commit_group;" ::: "memory")
#define CP_WAIT0()  asm volatile("cp.async.wait_group 0;" ::: "memory")

// split 4 fp32 -> packed hi bf16x2 pair + lo bf16x2 pair
__device__ __forceinline__ void split4(float4 f, uint32_t* hi, uint32_t* lo) {
    uint32_t x0 = __float_as_uint(f.x), x1 = __float_as_uint(f.y);
    uint32_t x2 = __float_as_uint(f.z), x3 = __float_as_uint(f.w);
    hi[0] = __byte_perm(x0, x1, 0x7632);
    hi[1] = __byte_perm(x2, x3, 0x7632);
    float l0 = f.x - __uint_as_float(x0 & 0xFFFF0000u);
    float l1 = f.y - __uint_as_float(x1 & 0xFFFF0000u);
    float l2 = f.z - __uint_as_float(x2 & 0xFFFF0000u);
    float l3 = f.w - __uint_as_float(x3 & 0xFFFF0000u);
    __nv_bfloat162 b0 = __floats2bfloat162_rn(l0, l1);
    __nv_bfloat162 b1 = __floats2bfloat162_rn(l2, l3);
    lo[0] = *reinterpret_cast<uint32_t*>(&b0);
    lo[1] = *reinterpret_cast<uint32_t*>(&b1);
}

// ===========================================================================
// bf16x3 split GEMM (NT) — unchanged from R4
// ===========================================================================
#define GBM 128
#define GBN 128
#define GKB 32
#define GSTRIDE 40
#define TILE_ELE (128 * GSTRIDE)
#define GEMM_SMEM (4 * TILE_ELE * 2)

__global__ __launch_bounds__(256) void gemm_bf16x3(const float* __restrict__ A,
                                                   const float* __restrict__ B,
                                                   float* __restrict__ C,
                                                   int M, int N, int K) {
    extern __shared__ __nv_bfloat16 sm[];
    __nv_bfloat16* sAhi = sm;
    __nv_bfloat16* sAlo = sm + TILE_ELE;
    __nv_bfloat16* sBhi = sm + 2 * TILE_ELE;
    __nv_bfloat16* sBlo = sm + 3 * TILE_ELE;

    const int tid = threadIdx.x;
    const int wid = tid >> 5;
    const int lane = tid & 31;
    const int wm = wid & 3;
    const int wn = wid >> 2;
    const int bm = blockIdx.y * GBM;
    const int bn = blockIdx.x * GBN;
    const int lrow = tid >> 3;
    const int lc4 = tid & 7;

    float acc[2][8][4];
#pragma unroll
    for (int i = 0; i < 2; i++)
#pragma unroll
        for (int j = 0; j < 8; j++)
#pragma unroll
            for (int q = 0; q < 4; q++) acc[i][j][q] = 0.f;

    const uint32_t sb = smem_u32(sm);
    const uint32_t aRow = wm * 32 + (lane & 15);
    const uint32_t aCol = (lane >> 4) * 8;
    const uint32_t aOffB = (aRow * GSTRIDE + aCol) * 2;
    const uint32_t addrAhi = sb + aOffB;
    const uint32_t addrAlo = sb + TILE_ELE * 2 + aOffB;
    const uint32_t bRow = wn * 64 + (lane & 7) + ((lane >> 4) & 1) * 8;
    const uint32_t bCol = ((lane >> 3) & 1) * 8;
    const uint32_t bOffB = (bRow * GSTRIDE + bCol) * 2;
    const uint32_t addrBhi = sb + 2 * TILE_ELE * 2 + bOffB;
    const uint32_t addrBlo = sb + 3 * TILE_ELE * 2 + bOffB;

    const int NC = K / GKB;
    float4 pfA[4], pfB[4];
#pragma unroll
    for (int u = 0; u < 4; ++u) {
        int row = lrow + u * 32;
        pfA[u] = *reinterpret_cast<const float4*>(&A[(size_t)(bm + row) * K + lc4 * 4]);
        pfB[u] = *reinterpret_cast<const float4*>(&B[(size_t)(bn + row) * K + lc4 * 4]);
    }

    for (int kc = 0; kc < NC; ++kc) {
#pragma unroll
        for (int u = 0; u < 4; ++u) {
            int row = lrow + u * 32;
            uint32_t hi[2], lo[2];
            uint32_t off = row * GSTRIDE + lc4 * 4;
            split4(pfA[u], hi, lo);
            *reinterpret_cast<uint2*>(&sAhi[off]) = make_uint2(hi[0], hi[1]);
            *reinterpret_cast<uint2*>(&sAlo[off]) = make_uint2(lo[0], lo[1]);
            split4(pfB[u], hi, lo);
            *reinterpret_cast<uint2*>(&sBhi[off]) = make_uint2(hi[0], hi[1]);
            *reinterpret_cast<uint2*>(&sBlo[off]) = make_uint2(lo[0], lo[1]);
        }
        __syncthreads();

        if (kc + 1 < NC) {
            const int k0 = (kc + 1) * GKB;
#pragma unroll
            for (int u = 0; u < 4; ++u) {
                int row = lrow + u * 32;
                pfA[u] = *reinterpret_cast<const float4*>(&A[(size_t)(bm + row) * K + k0 + lc4 * 4]);
                pfB[u] = *reinterpret_cast<const float4*>(&B[(size_t)(bn + row) * K + k0 + lc4 * 4]);
            }
        }

#pragma unroll
        for (int ks = 0; ks < 2; ++ks) {
            const uint32_t ko = ks * 32;
            uint32_t ah[2][4], al[2][4];
#pragma unroll
            for (int mt = 0; mt < 2; ++mt) {
                ldsm_x4(ah[mt], addrAhi + mt * (16 * GSTRIDE * 2) + ko);
                ldsm_x4(al[mt], addrAlo + mt * (16 * GSTRIDE * 2) + ko);
            }
            uint32_t bh[4][4], bl[4][4];
#pragma unroll
            for (int p = 0; p < 4; ++p) {
                ldsm_x4(bh[p], addrBhi + p * (16 * GSTRIDE * 2) + ko);
                ldsm_x4(bl[p], addrBlo + p * (16 * GSTRIDE * 2) + ko);
            }
#pragma unroll
            for (int mt = 0; mt < 2; ++mt)
#pragma unroll
                for (int nt = 0; nt < 8; ++nt) {
                    uint32_t h0 = bh[nt >> 1][(nt & 1) * 2];
                    uint32_t h1 = bh[nt >> 1][(nt & 1) * 2 + 1];
                    uint32_t l0 = bl[nt >> 1][(nt & 1) * 2];
                    uint32_t l1 = bl[nt >> 1][(nt & 1) * 2 + 1];
                    mma_bf16(acc[mt][nt], ah[mt], h0, h1);
                    mma_bf16(acc[mt][nt], ah[mt], l0, l1);
                    mma_bf16(acc[mt][nt], al[mt], h0, h1);
                }
        }
        __syncthreads();
    }

    const int g = lane >> 2;
    const int cc = (lane & 3) * 2;
#pragma unroll
    for (int mt = 0; mt < 2; ++mt) {
        int row0 = bm + wm * 32 + mt * 16 + g;
#pragma unroll
        for (int nt = 0; nt < 8; ++nt) {
            int col = bn + wn * 64 + nt * 8 + cc;
            *reinterpret_cast<float2*>(&C[(size_t)row0 * N + col]) =
                make_float2(acc[mt][nt][0], acc[mt][nt][1]);
            *reinterpret_cast<float2*>(&C[(size_t)(row0 + 8) * N + col]) =
                make_float2(acc[mt][nt][2], acc[mt][nt][3]);
        }
    }
}

// ===========================================================================
// fused RoPE + head-major split to bf16 hi/lo.  One thread: (t, head hh, i<64)
// handles elements i and i+64.  Q gets 1/sqrt(128) folded in.
// ===========================================================================
__global__ __launch_bounds__(256) void rope_split(const float* __restrict__ qkv,
        __nv_bfloat16* __restrict__ qhi, __nv_bfloat16* __restrict__ qlo,
        __nv_bfloat16* __restrict__ khi, __nv_bfloat16* __restrict__ klo,
        __nv_bfloat16* __restrict__ vhi, __nv_bfloat16* __restrict__ vlo) {
    int x = blockIdx.x * 256 + threadIdx.x;           // < TT*48*64
    int i = x & 63;
    int r = x >> 6;
    int hh = r % (NH + 2 * NKV);
    int t = r / (NH + 2 * NKV);
    int b = t >> 10;
    int s = t & (SEQ - 1);

    const float* base = qkv + (size_t)t * QKVD + hh * HD;
    float x1 = base[i];
    float x2 = base[i + 64];
    float y1, y2;
    if (hh < NH + NKV) {
        float invf = 1.0f / powf(10000.0f, (float)(2 * i) * (1.0f / (float)HD));
        float ang = (float)s * invf;
        float sn, cs;
        sincosf(ang, &sn, &cs);
        y1 = x1 * cs - x2 * sn;
        y2 = x2 * cs + x1 * sn;
    } else { y1 = x1; y2 = x2; }

    __nv_bfloat16 *dh, *dl;
    size_t off;
    if (hh < NH) {
        const float sc = 0.08838834764831845f;       // 128^-0.5
        y1 *= sc; y2 *= sc;
        off = ((size_t)(b * NH + hh) * SEQ + s) * HD;
        dh = qhi; dl = qlo;
    } else if (hh < NH + NKV) {
        off = ((size_t)(b * NKV + (hh - NH)) * SEQ + s) * HD;
        dh = khi; dl = klo;
    } else {
        off = ((size_t)(b * NKV + (hh - NH - NKV)) * SEQ + s) * HD;
        dh = vhi; dl = vlo;
    }
    uint32_t u1 = __float_as_uint(y1), u2 = __float_as_uint(y2);
    float h1 = __uint_as_float(u1 & 0xFFFF0000u);
    float h2 = __uint_as_float(u2 & 0xFFFF0000u);
    dh[off + i]      = __float2bfloat16(h1);     // exact (already truncated)
    dh[off + i + 64] = __float2bfloat16(h2);
    dl[off + i]      = __float2bfloat16(y1 - h1);
    dl[off + i + 64] = __float2bfloat16(y2 - h2);
}

// ===========================================================================
// Tensor-core causal GQA flash attention (bf16x3 split).
// Block: 128 q-rows, 8 warps (warp = 16 rows x full width). K-tiles of 64.
// cp.async double-buffered K/V smem; P kept in registers.
// ===========================================================================
#define AQ   128
#define AKT  64
#define ASTR 136                       // bf16 stride (272B = 17*16B, conflict-free)
#define Q_BYTES   (AQ * ASTR * 2)      // 34816 per tensor
#define KV_BYTES  (AKT * ASTR * 2)     // 17408 per tensor
#define KVBUF     (4 * KV_BYTES)       // 69632
#define ATT_SMEM  (2 * Q_BYTES + 2 * KVBUF)   // 208896

__global__ __launch_bounds__(256) void attn_mma(
        const __nv_bfloat16* __restrict__ Qhi, const __nv_bfloat16* __restrict__ Qlo,
        const __nv_bfloat16* __restrict__ Khi, const __nv_bfloat16* __restrict__ Klo,
        const __nv_bfloat16* __restrict__ Vhi, const __nv_bfloat16* __restrict__ Vlo,
        float* __restrict__ out) {
    extern __shared__ char sm8[];
    const uint32_t sb = smem_u32(sm8);
    const int tid = threadIdx.x, wid = tid >> 5, lane = tid & 31;
    const int qtile = gridDim.x - 1 - blockIdx.x;
    const int h = blockIdx.y, b = blockIdx.z;
    const int kvh = h >> 2;

    const size_t qbase = ((size_t)(b * NH + h) * SEQ + qtile * AQ) * HD;
    const size_t kbase = ((size_t)(b * NKV + kvh) * SEQ) * HD;

    // Q load (once): 128 rows x 16 chunks, hi+lo
    for (int i = tid; i < AQ * 16; i += 256) {
        int row = i >> 4, c = i & 15;
        uint32_t d = sb + row * (ASTR * 2) + c * 16;
        const size_t src = qbase + (size_t)row * HD + c * 8;
        cp16(d, Qhi + src);
        cp16(d + Q_BYTES, Qlo + src);
    }
    // K/V tile 0 into buffer 0
    {
        uint32_t dst0 = sb + 2 * Q_BYTES;
        for (int i = tid; i < AKT * 16; i += 256) {
            int row = i >> 4, c = i & 15;
            uint32_t d = dst0 + row * (ASTR * 2) + c * 16;
            const size_t src = kbase + (size_t)row * HD + c * 8;
            cp16(d,                Khi + src);
            cp16(d + KV_BYTES,     Klo + src);
            cp16(d + 2 * KV_BYTES, Vhi + src);
            cp16(d + 3 * KV_BYTES, Vlo + src);
        }
    }
    CP_COMMIT();

    float oacc[16][4];
#pragma unroll
    for (int n = 0; n < 16; n++)
#pragma unroll
        for (int q = 0; q < 4; q++) oacc[n][q] = 0.f;
    float m0 = -1e30f, m1 = -1e30f, l0 = 0.f, l1 = 0.f;

    // per-thread fragment addresses
    const uint32_t aRow = wid * 16 + (lane & 15);
    const uint32_t aColP = (lane >> 4) * 8;
    const uint32_t qAddr = sb + (aRow * ASTR + aColP) * 2;
    const uint32_t bRowP = (lane & 7) + ((lane >> 4) & 1) * 8;
    const uint32_t bColP = ((lane >> 3) & 1) * 8;
    const uint32_t vRowP = (lane & 7) + ((lane >> 3) & 1) * 8;
    const uint32_t vColP = (lane >> 4) * 8;

    const int nkt = 2 * qtile + 2;
    const int row0g = qtile * AQ + wid * 16 + (lane >> 2);

    for (int kt = 0; kt < nkt; ++kt) {
        const int s = kt & 1;
        CP_WAIT0();
        __syncthreads();
        if (kt + 1 < nkt) {
            uint32_t dst0 = sb + 2 * Q_BYTES + (s ^ 1) * KVBUF;
            const size_t kvoff = kbase + (size_t)(kt + 1) * AKT * HD;
            for (int i = tid; i < AKT * 16; i += 256) {
                int row = i >> 4, c = i & 15;
                uint32_t d = dst0 + row * (ASTR * 2) + c * 16;
                const size_t src = kvoff + (size_t)row * HD + c * 8;
                cp16(d,                Khi + src);
                cp16(d + KV_BYTES,     Klo + src);
                cp16(d + 2 * KV_BYTES, Vhi + src);
                cp16(d + 3 * KV_BYTES, Vlo + src);
            }
            CP_COMMIT();
        }

        const uint32_t kvb = sb + 2 * Q_BYTES + s * KVBUF;

        // ---- S = Q @ K^T (64 cols), bf16x3 ----
        float sacc[8][4];
#pragma unroll
        for (int n = 0; n < 8; n++)
#pragma unroll
            for (int q = 0; q < 4; q++) sacc[n][q] = 0.f;

#pragma unroll
        for (int ks = 0; ks < 8; ++ks) {
            uint32_t aq[4], aql[4];
            uint32_t qa = qAddr + ks * 32;
            ldsm_x4(aq, qa);
            ldsm_x4(aql, qa + Q_BYTES);
            uint32_t bh[4][4], bl[4][4];
#pragma unroll
            for (int p = 0; p < 4; ++p) {
                uint32_t ba = kvb + ((p * 16 + bRowP) * ASTR + ks * 16 + bColP) * 2;
                ldsm_x4(bh[p], ba);
                ldsm_x4(bl[p], ba + KV_BYTES);
            }
#pragma unroll
            for (int nt = 0; nt < 8; ++nt) {
                uint32_t h0 = bh[nt >> 1][(nt & 1) * 2];
                uint32_t h1 = bh[nt >> 1][(nt & 1) * 2 + 1];
                uint32_t q0 = bl[nt >> 1][(nt & 1) * 2];
                uint32_t q1 = bl[nt >> 1][(nt & 1) * 2 + 1];
                mma_bf16(sacc[nt], aq, h0, h1);
                mma_bf16(sacc[nt], aq, q0, q1);
                mma_bf16(sacc[nt], aql, h0, h1);
            }
        }

        // ---- causal mask (only tiles touching the diagonal) ----
        if (kt * AKT + AKT - 1 > qtile * AQ + wid * 16) {
            const int colb = kt * AKT + (lane & 3) * 2;
#pragma unroll
            for (int nt = 0; nt < 8; ++nt) {
                int c0 = colb + nt * 8;
                if (c0 > row0g)         sacc[nt][0] = -1e30f;
                if (c0 + 1 > row0g)     sacc[nt][1] = -1e30f;
                if (c0 > row0g + 8)     sacc[nt][2] = -1e30f;
                if (c0 + 1 > row0g + 8) sacc[nt][3] = -1e30f;
            }
        }

        // ---- online softmax ----
        float mx0 = -1e30f, mx1 = -1e30f;
#pragma unroll
        for (int nt = 0; nt < 8; ++nt) {
            mx0 = fmaxf(mx0, fmaxf(sacc[nt][0], sacc[nt][1]));
            mx1 = fmaxf(mx1, fmaxf(sacc[nt][2], sacc[nt][3]));
        }
        mx0 = fmaxf(mx0, __shfl_xor_sync(0xffffffffu, mx0, 1));
        mx0 = fmaxf(mx0, __shfl_xor_sync(0xffffffffu, mx0, 2));
        mx1 = fmaxf(mx1, __shfl_xor_sync(0xffffffffu, mx1, 1));
        mx1 = fmaxf(mx1, __shfl_xor_sync(0xffffffffu, mx1, 2));
        float nm0 = fmaxf(m0, mx0), nm1 = fmaxf(m1, mx1);
        float r0 = 0.f, r1 = 0.f;
#pragma unroll
        for (int nt = 0; nt < 8; ++nt) {
            sacc[nt][0] = __expf(sacc[nt][0] - nm0);
            sacc[nt][1] = __expf(sacc[nt][1] - nm0);
            sacc[nt][2] = __expf(sacc[nt][2] - nm1);
            sacc[nt][3] = __expf(sacc[nt][3] - nm1);
            r0 += sacc[nt][0] + sacc[nt][1];
            r1 += sacc[nt][2] + sacc[nt][3];
        }
        r0 += __shfl_xor_sync(0xffffffffu, r0, 1);
        r0 += __shfl_xor_sync(0xffffffffu, r0, 2);
        r1 += __shfl_xor_sync(0xffffffffu, r1, 1);
        r1 += __shfl_xor_sync(0xffffffffu, r1, 2);
        float a0 = __expf(m0 - nm0), a1 = __expf(m1 - nm1);
        l0 = l0 * a0 + r0;
        l1 = l1 * a1 + r1;
        m0 = nm0; m1 = nm1;
#pragma unroll
        for (int n = 0; n < 16; ++n) {
            oacc[n][0] *= a0; oacc[n][1] *= a0;
            oacc[n][2] *= a1; oacc[n][3] *= a1;
        }

        // ---- pack P (hi trunc / lo residual) ----
        uint32_t ph[8][2], pl[8][2];
#pragma unroll
        for (int nt = 0; nt < 8; ++nt) {
            uint32_t u0 = __float_as_uint(sacc[nt][0]);
            uint32_t u1 = __float_as_uint(sacc[nt][1]);
            uint32_t u2 = __float_as_uint(sacc[nt][2]);
            uint32_t u3 = __float_as_uint(sacc[nt][3]);
            ph[nt][0] = __byte_perm(u0, u1, 0x7632);
            ph[nt][1] = __byte_perm(u2, u3, 0x7632);
            float e0 = sacc[nt][0] - __uint_as_float(u0 & 0xFFFF0000u);
            float e1 = sacc[nt][1] - __uint_as_float(u1 & 0xFFFF0000u);
            float e2 = sacc[nt][2] - __uint_as_float(u2 & 0xFFFF0000u);
            float e3 = sacc[nt][3] - __uint_as_float(u3 & 0xFFFF0000u);
            __nv_bfloat162 p01 = __floats2bfloat162_rn(e0, e1);
            __nv_bfloat162 p23 = __floats2bfloat162_rn(e2, e3);
            pl[nt][0] = *reinterpret_cast<uint32_t*>(&p01);
            pl[nt][1] = *reinterpret_cast<uint32_t*>(&p23);
        }

        // ---- O += P @ V (128 cols), bf16x3 ----
        const uint32_t vbase = kvb + 2 * KV_BYTES;
#pragma unroll
        for (int kk = 0; kk < 4; ++kk) {
            uint32_t pa[4]  = { ph[2 * kk][0], ph[2 * kk][1], ph[2 * kk + 1][0], ph[2 * kk + 1][1] };
            uint32_t pal[4] = { pl[2 * kk][0], pl[2 * kk][1], pl[2 * kk + 1][0], pl[2 * kk + 1][1] };
#pragma unroll
            for (int nt = 0; nt < 8; ++nt) {
                uint32_t va = vbase + ((kk * 16 + vRowP) * ASTR + nt * 16 + vColP) * 2;
                uint32_t vh[4], vl[4];
                ldsm_x4_t(vh, va);
                ldsm_x4_t(vl, va + KV_BYTES);
                mma_bf16(oacc[2 * nt],     pa,  vh[0], vh[1]);
                mma_bf16(oacc[2 * nt],     pa,  vl[0], vl[1]);
                mma_bf16(oacc[2 * nt],     pal, vh[0], vh[1]);
                mma_bf16(oacc[2 * nt + 1], pa,  vh[2], vh[3]);
                mma_bf16(oacc[2 * nt + 1], pa,  vl[2], vl[3]);
                mma_bf16(oacc[2 * nt + 1], pal, vh[2], vh[3]);
            }
        }
    }

    // ---- epilogue ----
    float inv0 = 1.0f / l0, inv1 = 1.0f / l1;
    const int trow = b * SEQ + row0g;            // global token of row g
    const int cc = (lane & 3) * 2;
#pragma unroll
    for (int nt = 0; nt < 16; ++nt) {
        int col = h * HD + nt * 8 + cc;
        *reinterpret_cast<float2*>(&out[(size_t)trow * HID + col]) =
            make_float2(oacc[nt][0] * inv0, oacc[nt][1] * inv0);
        *reinterpret_cast<float2*>(&out[(size_t)(trow + 8) * HID + col]) =
            make_float2(oacc[nt][2] * inv1, oacc[nt][3] * inv1);
    }
}

// ---------------------------------------------------------------------------
extern "C" void kernel_launch(void* const* d_in, const int* in_sizes, int n_in,
                              void* d_out, int out_size) {
    const float* hs    = (const float*)d_in[0];   // [4096, 4096]
    const float* w_qkv = (const float*)d_in[1];   // [6144, 4096]
    const float* w_o   = (const float*)d_in[2];   // [4096, 4096]
    float* out = (float*)d_out;                   // [4096, 4096]

    float *qkv = nullptr, *attn = nullptr;
    __nv_bfloat16 *qhi, *qlo, *khi, *klo, *vhi, *vlo;
    cudaGetSymbolAddress((void**)&qkv, g_qkv);
    cudaGetSymbolAddress((void**)&attn, g_attn);
    cudaGetSymbolAddress((void**)&qhi, g_qhi);
    cudaGetSymbolAddress((void**)&qlo, g_qlo);
    cudaGetSymbolAddress((void**)&khi, g_khi);
    cudaGetSymbolAddress((void**)&klo, g_klo);
    cudaGetSymbolAddress((void**)&vhi, g_vhi);
    cudaGetSymbolAddress((void**)&vlo, g_vlo);

    cudaFuncSetAttribute(gemm_bf16x3, cudaFuncAttributeMaxDynamicSharedMemorySize, GEMM_SMEM);
    cudaFuncSetAttribute(attn_mma, cudaFuncAttributeMaxDynamicSharedMemorySize, ATT_SMEM);

    // 1) QKV projection (tensor cores, bf16x3)
    {
        dim3 grid(QKVD / GBN, TT / GBM);
        gemm_bf16x3<<<grid, 256, GEMM_SMEM>>>(hs, w_qkv, qkv, TT, QKVD, HID);
    }
    // 2) fused RoPE + split to bf16 hi/lo (head-major)
    {
        int total = TT * (NH + 2 * NKV) * 64;
        rope_split<<<total / 256, 256>>>(qkv, qhi, qlo, khi, klo, vhi, vlo);
    }
    // 3) tensor-core causal GQA attention -> g_attn
    {
        dim3 grid(SEQ / AQ, NH, NB);
        attn_mma<<<grid, 256, ATT_SMEM>>>(qhi, qlo, khi, klo, vhi, vlo, attn);
    }
    // 4) output projection (tensor cores, bf16x3)
    {
        dim3 grid(HID / GBN, TT / GBM);
        gemm_bf16x3<<<grid, 256, GEMM_SMEM>>>(attn, w_o, out, TT, HID, HID);
    }
}